// round 2
// baseline (speedup 1.0000x reference)
#include <cuda_runtime.h>

#define OMEGA0 30.0f
#define HDIM 32
#define PADD 36                 // padded d-stride (floats): 144B lane stride, LDS.128 conflict-free
#define KSTRIDE (HDIM * PADD)   // 1152 floats per k-slice

// SMEM: W3s [32][32][36] + W2s [32*32] + W1s [32]
#define SMEM_FLOATS (32 * KSTRIDE + 1024 + 32)

__global__ __launch_bounds__(512, 1)
void ckconv_side_kernel(const float* __restrict__ emb,     // [N, 32] gathered embedding table
                        const float* __restrict__ t_node,  // [N]     node times
                        const float* __restrict__ edges_t, // [E]
                        const int*   __restrict__ gidx,    // [E] gather index (same table for t and emb)
                        const int*   __restrict__ sidx,    // [E] segment index (other side)
                        const float* __restrict__ W1,      // [32]
                        const float* __restrict__ W2,      // [32,32]
                        const float* __restrict__ W3,      // [32,1024]
                        float*       __restrict__ out,     // [Nseg, 32]
                        int E)
{
    extern __shared__ float sm[];
    float* W3s = sm;                      // 32*1152
    float* W2s = sm + 32 * KSTRIDE;       // 1024
    float* W1s = W2s + 1024;              // 32

    const int tid = threadIdx.x;

    // Stage weights. W3 row-major [k, j=h*32+d] -> padded [k][h][d]
    for (int j = tid; j < 32 * 1024; j += blockDim.x) {
        int k = j >> 10;
        int r = j & 1023;
        int h = r >> 5;
        int d = r & 31;
        W3s[k * KSTRIDE + h * PADD + d] = W3[j];
    }
    for (int j = tid; j < 1024; j += blockDim.x) W2s[j] = W2[j];
    if (tid < 32) W1s[tid] = W1[tid];
    __syncthreads();

    const int lane    = tid & 31;
    const int gwarp   = blockIdx.x * (blockDim.x >> 5) + (tid >> 5);
    const int nwarps  = gridDim.x * (blockDim.x >> 5);
    const int npairs  = (E + 1) >> 1;

    const float  w1j  = W1s[lane];
    const float4* emb4 = reinterpret_cast<const float4*>(emb);

    #pragma unroll 1
    for (int p = gwarp; p < npairs; p += nwarps) {
        const int e0 = 2 * p;
        const int e1 = e0 + 1;
        const bool has1 = (e1 < E);   // uniform across warp

        const int g0 = gidx[e0];
        const int s0 = sidx[e0];
        const float t0 = t_node[g0] - edges_t[e0];
        const int g1 = has1 ? gidx[e1] : g0;
        const int s1 = has1 ? sidx[e1] : s0;
        const float t1 = has1 ? (t_node[g1] - edges_t[e1]) : t0;

        // Gathered embeddings, broadcast-loaded into registers (32 floats each edge)
        float4 em0[8], em1[8];
        #pragma unroll
        for (int i = 0; i < 8; i++) {
            em0[i] = emb4[(size_t)g0 * 8 + i];
            em1[i] = emb4[(size_t)g1 * 8 + i];
        }

        // Layer 1: lane j owns channel j
        const float h1_0 = sinf(OMEGA0 * t0 * w1j);
        const float h1_1 = sinf(OMEGA0 * t1 * w1j);

        // Layer 2: h2[j] = sin(omega * dot(h1, W2[:, j]))
        float a0 = 0.f, a1 = 0.f;
        #pragma unroll
        for (int k = 0; k < 32; k++) {
            const float b0 = __shfl_sync(0xffffffffu, h1_0, k);
            const float b1 = __shfl_sync(0xffffffffu, h1_1, k);
            const float w  = W2s[k * 32 + lane];    // consecutive lanes -> conflict-free
            a0 = fmaf(b0, w, a0);
            a1 = fmaf(b1, w, a1);
        }
        const float h2_0 = sinf(OMEGA0 * a0);
        const float h2_1 = sinf(OMEGA0 * a1);

        // Layer 3 fused with einsum:
        // msg[h=lane] = sum_k h2[k] * sum_d W3[k][h][d] * emb[d]
        // Two independent accumulator pairs to shorten the FMA dependency chain.
        float m0a = 0.f, m1a = 0.f, m0b = 0.f, m1b = 0.f;
        #pragma unroll 4
        for (int k = 0; k < 32; k += 2) {
            const float c0a = __shfl_sync(0xffffffffu, h2_0, k);
            const float c1a = __shfl_sync(0xffffffffu, h2_1, k);
            const float c0b = __shfl_sync(0xffffffffu, h2_0, k + 1);
            const float c1b = __shfl_sync(0xffffffffu, h2_1, k + 1);
            const float4* wka = reinterpret_cast<const float4*>(W3s + k * KSTRIDE + lane * PADD);
            const float4* wkb = reinterpret_cast<const float4*>(W3s + (k + 1) * KSTRIDE + lane * PADD);
            float d0a = 0.f, d1a = 0.f, d0b = 0.f, d1b = 0.f;
            #pragma unroll
            for (int q = 0; q < 8; q++) {
                const float4 wa = wka[q];           // one LDS.128 feeds 8 FMAs
                d0a += wa.x * em0[q].x + wa.y * em0[q].y + wa.z * em0[q].z + wa.w * em0[q].w;
                d1a += wa.x * em1[q].x + wa.y * em1[q].y + wa.z * em1[q].z + wa.w * em1[q].w;
            }
            #pragma unroll
            for (int q = 0; q < 8; q++) {
                const float4 wb = wkb[q];
                d0b += wb.x * em0[q].x + wb.y * em0[q].y + wb.z * em0[q].z + wb.w * em0[q].w;
                d1b += wb.x * em1[q].x + wb.y * em1[q].y + wb.z * em1[q].z + wb.w * em1[q].w;
            }
            m0a = fmaf(c0a, d0a, m0a);
            m1a = fmaf(c1a, d1a, m1a);
            m0b = fmaf(c0b, d0b, m0b);
            m1b = fmaf(c1b, d1b, m1b);
        }
        const float m0 = m0a + m0b;
        const float m1 = m1a + m1b;

        atomicAdd(&out[(size_t)s0 * 32 + lane], m0);
        if (has1) atomicAdd(&out[(size_t)s1 * 32 + lane], m1);
    }
}

extern "C" void kernel_launch(void* const* d_in, const int* in_sizes, int n_in,
                              void* d_out, int out_size)
{
    const float* u_emb   = (const float*)d_in[0];   // [U,32]
    const float* i_emb   = (const float*)d_in[1];   // [I,32]
    const int*   upt     = (const int*)  d_in[2];   // [E]
    const int*   ipt     = (const int*)  d_in[3];   // [E]
    const float* edges_t = (const float*)d_in[4];   // [E]
    const float* u_t     = (const float*)d_in[5];   // [U]
    const float* i_t     = (const float*)d_in[6];   // [I]
    const float* Wu1     = (const float*)d_in[7];
    const float* Wu2     = (const float*)d_in[8];
    const float* Wu3     = (const float*)d_in[9];
    const float* Wi1     = (const float*)d_in[10];
    const float* Wi2     = (const float*)d_in[11];
    const float* Wi3     = (const float*)d_in[12];

    const int E = in_sizes[4];
    const int U = in_sizes[5];

    float* out = (float*)d_out;

    const size_t smem = SMEM_FLOATS * sizeof(float);
    cudaFuncSetAttribute(ckconv_side_kernel,
                         cudaFuncAttributeMaxDynamicSharedMemorySize, (int)smem);

    // Output is poisoned; segment-sum accumulates -> zero it first.
    cudaMemsetAsync(d_out, 0, (size_t)out_size * sizeof(float));

    const int grid = 148;     // 1 block/SM (151.7 KB smem)
    const int threads = 512;

    // hLu: item kernels (Wi, relative_i = i_t[item]-edges_t) applied to i_embedded[item],
    //      segment-summed by user index.
    ckconv_side_kernel<<<grid, threads, smem>>>(
        i_emb, i_t, edges_t, ipt, upt, Wi1, Wi2, Wi3, out, E);

    // hLi: user kernels (Wu, relative_u) applied to u_embedded[user], summed by item index.
    ckconv_side_kernel<<<grid, threads, smem>>>(
        u_emb, u_t, edges_t, upt, ipt, Wu1, Wu2, Wu3, out + (size_t)U * 32, E);
}